// round 1
// baseline (speedup 1.0000x reference)
#include <cuda_runtime.h>
#include <math.h>

#define NN 6000
#define EE 100000

// ---------------- scratch (device globals; no allocations allowed) -------------
__device__ float g_H[2 * NN * 64];     // per-relation H matrices (also holds W0 for layer 0)
__device__ float g_base[NN * 64];      // x @ root
__device__ float g_xA[NN * 64];
__device__ float g_xB[NN * 64];
__device__ float g_Wr[2 * 64 * 64];    // small relation weights for layers 1-3
__device__ float g_h[NN * 512];        // GAT projected features
__device__ float g_xg[NN * 512];       // GAT output
__device__ float g_ab[NN * 256];       // [A | B] for edge MLP
__device__ float g_asv[NN];
__device__ float g_adv[NN];
__device__ float g_cnt[NN * 2];        // per-relation in-counts (float)
__device__ int   g_deg[NN];
__device__ int   g_rowptr[NN + 1];
__device__ int   g_cursor[NN];
__device__ int   g_csrc[EE];
__device__ int   g_ctype[EE];

// ---------------- CSR build ----------------------------------------------------
__global__ void zero_kernel(int* deg, float* cnt) {
    int i = blockIdx.x * blockDim.x + threadIdx.x;
    if (i < NN) deg[i] = 0;
    if (i < 2 * NN) cnt[i] = 0.f;
}

__global__ void count_kernel(const int* __restrict__ ei, const int* __restrict__ et,
                             int* deg, float* cnt) {
    int e = blockIdx.x * blockDim.x + threadIdx.x;
    if (e >= EE) return;
    int d = ei[EE + e];
    atomicAdd(&deg[d], 1);
    atomicAdd(&cnt[d * 2 + et[e]], 1.0f);
}

__global__ void scan_kernel(const int* __restrict__ deg, int* rowptr, int* cursor) {
    __shared__ int sdata[1024];
    int t = threadIdx.x;
    int base = t * 6;
    int loc[6];
    int sum = 0;
#pragma unroll
    for (int i = 0; i < 6; i++) {
        int idx = base + i;
        int v = (idx < NN) ? deg[idx] : 0;
        loc[i] = sum;
        sum += v;
    }
    sdata[t] = sum;
    __syncthreads();
    for (int off = 1; off < 1024; off <<= 1) {
        int v = (t >= off) ? sdata[t - off] : 0;
        __syncthreads();
        sdata[t] += v;
        __syncthreads();
    }
    int excl = sdata[t] - sum;
#pragma unroll
    for (int i = 0; i < 6; i++) {
        int idx = base + i;
        if (idx < NN) { rowptr[idx] = excl + loc[i]; cursor[idx] = excl + loc[i]; }
    }
    if (t == 1023) rowptr[NN] = sdata[1023];
}

__global__ void fill_kernel(const int* __restrict__ ei, const int* __restrict__ et,
                            int* cursor, int* csrc, int* ctype) {
    int e = blockIdx.x * blockDim.x + threadIdx.x;
    if (e >= EE) return;
    int s = ei[e];
    int d = ei[EE + e];
    int pos = atomicAdd(&cursor[d], 1);
    csrc[pos] = s;
    ctype[pos] = et[e];
}

// ---------------- RGCN ---------------------------------------------------------
// Wr[r][i][o] = sum_b comp[r,b] * basis[b][i][o]   (io flattened)
__global__ void wcomp_kernel(const float* __restrict__ basis, const float* __restrict__ comp,
                             float* __restrict__ Wr, int io_size) {
    int idx = blockIdx.x * blockDim.x + threadIdx.x;
    int total = 2 * io_size;
    if (idx >= total) return;
    int r = idx / io_size;
    int io = idx - r * io_size;
    float s = 0.f;
#pragma unroll
    for (int b = 0; b < 4; b++) s += comp[r * 4 + b] * basis[b * io_size + io];
    Wr[idx] = s;
}

// H[r] = x @ Wr[r], base = x @ root    (block handles blockDim.y nodes)
__global__ void dense_rgcn(const float* __restrict__ x, const float* __restrict__ Wr,
                           const float* __restrict__ root,
                           float* __restrict__ H, float* __restrict__ base,
                           int in, int out) {
    __shared__ float xs[4][64];
    int m = threadIdx.y;
    int n = blockIdx.x * blockDim.y + m;
    int o = threadIdx.x;
    for (int i = o; i < in; i += out) xs[m][i] = x[n * in + i];
    __syncthreads();
    float a0 = 0.f, a1 = 0.f, ab = 0.f;
    for (int i = 0; i < in; i++) {
        float xv = xs[m][i];
        a0 += xv * Wr[i * out + o];
        a1 += xv * Wr[(in + i) * out + o];
        ab += xv * root[i * out + o];
    }
    H[n * out + o] = a0;
    H[(NN + n) * out + o] = a1;
    base[n * out + o] = ab;
}

// per-node per-relation mean aggregation + tanh
__global__ void agg_rgcn(const float* __restrict__ H, const float* __restrict__ base,
                         const float* __restrict__ bias, const float* __restrict__ cnt,
                         const int* __restrict__ rowptr, const int* __restrict__ csrc,
                         const int* __restrict__ ctype,
                         float* __restrict__ xout, int out) {
    int m = threadIdx.y;
    int n = blockIdx.x * blockDim.y + m;
    int o = threadIdx.x;
    float a0 = 0.f, a1 = 0.f;
    int e0 = rowptr[n], e1 = rowptr[n + 1];
    for (int e = e0; e < e1; e++) {
        int s = csrc[e];
        int t = ctype[e];
        float v = H[(t * NN + s) * out + o];
        if (t == 0) a0 += v; else a1 += v;
    }
    float c0 = fmaxf(cnt[n * 2 + 0], 1.f);
    float c1 = fmaxf(cnt[n * 2 + 1], 1.f);
    xout[n * out + o] = tanhf(base[n * out + o] + bias[o] + a0 / c0 + a1 / c1);
}

// ---------------- GAT ----------------------------------------------------------
__device__ __forceinline__ float lrelu02(float a) { return a > 0.f ? a : 0.2f * a; }

__global__ void gat_h_kernel(const float* __restrict__ x, const float* __restrict__ gw,
                             const float* __restrict__ a_s, const float* __restrict__ a_d,
                             float* __restrict__ h, float* __restrict__ asv, float* __restrict__ adv) {
    __shared__ float xs[32];
    __shared__ float r1[512];
    __shared__ float r2[512];
    int n = blockIdx.x;
    int c = threadIdx.x;
    if (c < 32) xs[c] = x[n * 32 + c];
    __syncthreads();
    float hv = 0.f;
#pragma unroll
    for (int i = 0; i < 32; i++) hv += xs[i] * gw[i * 512 + c];
    h[n * 512 + c] = hv;
    r1[c] = hv * a_s[c];
    r2[c] = hv * a_d[c];
    __syncthreads();
    for (int off = 256; off > 0; off >>= 1) {
        if (c < off) { r1[c] += r1[c + off]; r2[c] += r2[c + off]; }
        __syncthreads();
    }
    if (c == 0) { asv[n] = r1[0]; adv[n] = r2[0]; }
}

__global__ void gat_agg_kernel(const float* __restrict__ h, const float* __restrict__ asv,
                               const float* __restrict__ adv,
                               const int* __restrict__ rowptr, const int* __restrict__ csrc,
                               const float* __restrict__ gbias, float* __restrict__ xout) {
    int n = blockIdx.x;
    int t = threadIdx.x;  // 128 threads, 4 consecutive cols each (float4)
    int e0 = rowptr[n], e1 = rowptr[n + 1];
    float advn = adv[n];
    float aself = lrelu02(asv[n] + advn);
    // pass 1: max
    float lm = aself;
    for (int e = e0 + t; e < e1; e += 128) lm = fmaxf(lm, lrelu02(asv[csrc[e]] + advn));
    __shared__ float sred[128];
    sred[t] = lm;
    __syncthreads();
    for (int off = 64; off > 0; off >>= 1) {
        if (t < off) sred[t] = fmaxf(sred[t], sred[t + off]);
        __syncthreads();
    }
    float m = sred[0];
    // pass 2: exp staged in shared (one exp per edge), accumulate
    __shared__ float sEx[128];
    __shared__ int sSrc[128];
    float4 acc = make_float4(0.f, 0.f, 0.f, 0.f);
    float denom = 0.f;
    for (int eb = e0; eb < e1; eb += 128) {
        int cnt = min(128, e1 - eb);
        __syncthreads();
        if (t < cnt) {
            int s = csrc[eb + t];
            sSrc[t] = s;
            sEx[t] = expf(lrelu02(asv[s] + advn) - m);
        }
        __syncthreads();
        for (int j = 0; j < cnt; j++) {
            float ex = sEx[j];
            const float4* hr = reinterpret_cast<const float4*>(h + (size_t)sSrc[j] * 512);
            float4 v = hr[t];
            acc.x += ex * v.x; acc.y += ex * v.y; acc.z += ex * v.z; acc.w += ex * v.w;
            denom += ex;
        }
    }
    // self loop
    float exs = expf(aself - m);
    denom += exs;
    {
        const float4* hn = reinterpret_cast<const float4*>(h + (size_t)n * 512);
        float4 v = hn[t];
        acc.x += exs * v.x; acc.y += exs * v.y; acc.z += exs * v.z; acc.w += exs * v.w;
    }
    float inv = 1.f / fmaxf(denom, 1e-16f);
    float4 g = reinterpret_cast<const float4*>(gbias)[t];
    float4 o;
    o.x = fmaxf(acc.x * inv + g.x, 0.f);
    o.y = fmaxf(acc.y * inv + g.y, 0.f);
    o.z = fmaxf(acc.z * inv + g.z, 0.f);
    o.w = fmaxf(acc.w * inv + g.w, 0.f);
    reinterpret_cast<float4*>(xout + (size_t)n * 512)[t] = o;
}

// ---------------- edge MLP ------------------------------------------------------
// AB[n, 0:128] = xg[n] @ w1[0:512, :]; AB[n, 128:256] = xg[n] @ w1[512:1024, :]
__global__ void gemm_ab_kernel(const float* __restrict__ xg, const float* __restrict__ w1,
                               float* __restrict__ ab) {
    __shared__ float xs[16][32];
    __shared__ float ws[32][256];
    int c = threadIdx.x;  // 256
    int n0 = blockIdx.x * 16;
    float acc[16];
#pragma unroll
    for (int i = 0; i < 16; i++) acc[i] = 0.f;
    for (int k0 = 0; k0 < 512; k0 += 32) {
        __syncthreads();
        for (int i = c; i < 16 * 32; i += 256) {
            int mm = i >> 5, kk = i & 31;
            xs[mm][kk] = xg[(size_t)(n0 + mm) * 512 + k0 + kk];
        }
        for (int i = c; i < 32 * 256; i += 256) {
            int kk = i >> 8, cc = i & 255;
            int krow = k0 + kk + ((cc < 128) ? 0 : 512);
            int col = (cc < 128) ? cc : cc - 128;
            ws[kk][cc] = w1[krow * 128 + col];
        }
        __syncthreads();
#pragma unroll 8
        for (int kk = 0; kk < 32; kk++) {
            float wv = ws[kk][c];
#pragma unroll
            for (int mm = 0; mm < 16; mm++) acc[mm] += xs[mm][kk] * wv;
        }
    }
#pragma unroll
    for (int mm = 0; mm < 16; mm++) ab[(size_t)(n0 + mm) * 256 + c] = acc[mm];
}

// warp per edge: out = sigmoid( relu(A[src]+B[dst]+b1) . w2 + b2 )
__global__ void edge_kernel(const int* __restrict__ ei, const float* __restrict__ ab,
                            const float* __restrict__ b1, const float* __restrict__ w2,
                            const float* __restrict__ b2, float* __restrict__ out) {
    int gid = blockIdx.x * blockDim.x + threadIdx.x;
    int e = gid >> 5;
    int lane = gid & 31;
    if (e >= EE) return;
    int s = ei[e];
    int d = ei[EE + e];
    const float* A = ab + (size_t)s * 256;
    const float* B = ab + (size_t)d * 256 + 128;
    float acc = 0.f;
#pragma unroll
    for (int k = 0; k < 4; k++) {
        int j = lane + k * 32;
        float hv = fmaxf(A[j] + B[j] + b1[j], 0.f);
        acc += hv * w2[j];
    }
#pragma unroll
    for (int off = 16; off > 0; off >>= 1) acc += __shfl_down_sync(0xffffffffu, acc, off);
    if (lane == 0) out[e] = 1.f / (1.f + expf(-(acc + b2[0])));
}

// ---------------- launch ---------------------------------------------------------
extern "C" void kernel_launch(void* const* d_in, const int* in_sizes, int n_in,
                              void* d_out, int out_size) {
    const float *basis[4], *comp[4], *root[4], *rbias[4];
    const float *gat_w, *att_s, *att_d, *gat_b, *w1, *b1, *w2, *b2;
    const int *ei, *et;

    if (in_sizes[0] == 2 * EE) {
        // signature order: edge_index, edge_type, (basis,comp,root,rbias)x4, gat..., mlp...
        ei = (const int*)d_in[0];
        et = (const int*)d_in[1];
        int k = 2;
        for (int l = 0; l < 4; l++) {
            basis[l] = (const float*)d_in[k++];
            comp[l]  = (const float*)d_in[k++];
            root[l]  = (const float*)d_in[k++];
            rbias[l] = (const float*)d_in[k++];
        }
        gat_w = (const float*)d_in[18]; att_s = (const float*)d_in[19];
        att_d = (const float*)d_in[20]; gat_b = (const float*)d_in[21];
        w1 = (const float*)d_in[22]; b1 = (const float*)d_in[23];
        w2 = (const float*)d_in[24]; b2 = (const float*)d_in[25];
    } else if (in_sizes[0] == 4 * NN * 32) {
        // insertion order: (basis,comp,root,rbias)x4, gat..., mlp..., edge_index, edge_type
        int k = 0;
        for (int l = 0; l < 4; l++) {
            basis[l] = (const float*)d_in[k++];
            comp[l]  = (const float*)d_in[k++];
            root[l]  = (const float*)d_in[k++];
            rbias[l] = (const float*)d_in[k++];
        }
        gat_w = (const float*)d_in[16]; att_s = (const float*)d_in[17];
        att_d = (const float*)d_in[18]; gat_b = (const float*)d_in[19];
        w1 = (const float*)d_in[20]; b1 = (const float*)d_in[21];
        w2 = (const float*)d_in[22]; b2 = (const float*)d_in[23];
        ei = (const int*)d_in[24]; et = (const int*)d_in[25];
    } else {
        // alphabetical: b1,b2,basis0-3,comp0-3,edge_index,edge_type,
        //               gat_att_dst,gat_att_src,gat_bias,gat_w,rbias0-3,root0-3,w1,w2
        b1 = (const float*)d_in[0]; b2 = (const float*)d_in[1];
        for (int l = 0; l < 4; l++) basis[l] = (const float*)d_in[2 + l];
        for (int l = 0; l < 4; l++) comp[l] = (const float*)d_in[6 + l];
        ei = (const int*)d_in[10]; et = (const int*)d_in[11];
        att_d = (const float*)d_in[12]; att_s = (const float*)d_in[13];
        gat_b = (const float*)d_in[14]; gat_w = (const float*)d_in[15];
        for (int l = 0; l < 4; l++) rbias[l] = (const float*)d_in[16 + l];
        for (int l = 0; l < 4; l++) root[l] = (const float*)d_in[20 + l];
        w1 = (const float*)d_in[24]; w2 = (const float*)d_in[25];
    }

    float *H, *base, *xA, *xB, *Wr, *h, *xg, *ab, *asv, *adv, *cnt;
    int *deg, *rowptr, *cursor, *csrc, *ctype;
    cudaGetSymbolAddress((void**)&H, g_H);
    cudaGetSymbolAddress((void**)&base, g_base);
    cudaGetSymbolAddress((void**)&xA, g_xA);
    cudaGetSymbolAddress((void**)&xB, g_xB);
    cudaGetSymbolAddress((void**)&Wr, g_Wr);
    cudaGetSymbolAddress((void**)&h, g_h);
    cudaGetSymbolAddress((void**)&xg, g_xg);
    cudaGetSymbolAddress((void**)&ab, g_ab);
    cudaGetSymbolAddress((void**)&asv, g_asv);
    cudaGetSymbolAddress((void**)&adv, g_adv);
    cudaGetSymbolAddress((void**)&cnt, g_cnt);
    cudaGetSymbolAddress((void**)&deg, g_deg);
    cudaGetSymbolAddress((void**)&rowptr, g_rowptr);
    cudaGetSymbolAddress((void**)&cursor, g_cursor);
    cudaGetSymbolAddress((void**)&csrc, g_csrc);
    cudaGetSymbolAddress((void**)&ctype, g_ctype);

    float* out = (float*)d_out;

    // ---- CSR build (once per launch; shared by all layers) ----
    zero_kernel<<<(2 * NN + 255) / 256, 256>>>(deg, cnt);
    count_kernel<<<(EE + 255) / 256, 256>>>(ei, et, deg, cnt);
    scan_kernel<<<1, 1024>>>(deg, rowptr, cursor);
    fill_kernel<<<(EE + 255) / 256, 256>>>(ei, et, cursor, csrc, ctype);

    // ---- Layer 0 (x = I shortcut): H = W0 (basis-combined), base = root0 ----
    wcomp_kernel<<<(2 * NN * 32 + 255) / 256, 256>>>(basis[0], comp[0], H, NN * 32);
    agg_rgcn<<<NN / 4, dim3(32, 4)>>>(H, root[0], rbias[0], cnt, rowptr, csrc, ctype, xA, 32);

    // ---- Layer 1: 32 -> 64 ----
    wcomp_kernel<<<(2 * 32 * 64 + 255) / 256, 256>>>(basis[1], comp[1], Wr, 32 * 64);
    dense_rgcn<<<NN / 2, dim3(64, 2)>>>(xA, Wr, root[1], H, base, 32, 64);
    agg_rgcn<<<NN / 2, dim3(64, 2)>>>(H, base, rbias[1], cnt, rowptr, csrc, ctype, xB, 64);

    // ---- Layer 2: 64 -> 64 ----
    wcomp_kernel<<<(2 * 64 * 64 + 255) / 256, 256>>>(basis[2], comp[2], Wr, 64 * 64);
    dense_rgcn<<<NN / 2, dim3(64, 2)>>>(xB, Wr, root[2], H, base, 64, 64);
    agg_rgcn<<<NN / 2, dim3(64, 2)>>>(H, base, rbias[2], cnt, rowptr, csrc, ctype, xA, 64);

    // ---- Layer 3: 64 -> 32 ----
    wcomp_kernel<<<(2 * 64 * 32 + 255) / 256, 256>>>(basis[3], comp[3], Wr, 64 * 32);
    dense_rgcn<<<NN / 4, dim3(32, 4)>>>(xA, Wr, root[3], H, base, 64, 32);
    agg_rgcn<<<NN / 4, dim3(32, 4)>>>(H, base, rbias[3], cnt, rowptr, csrc, ctype, xB, 32);

    // ---- GAT ----
    gat_h_kernel<<<NN, 512>>>(xB, gat_w, att_s, att_d, h, asv, adv);
    gat_agg_kernel<<<NN, 128>>>(h, asv, adv, rowptr, csrc, gat_b, xg);

    // ---- edge MLP (factorized: feat@w1 = A[src] + B[dst]) ----
    gemm_ab_kernel<<<NN / 16, 256>>>(xg, w1, ab);
    edge_kernel<<<(EE * 32 + 255) / 256, 256>>>(ei, ab, b1, w2, b2, out);
}

// round 2
// speedup vs baseline: 1.0648x; 1.0648x over previous
#include <cuda_runtime.h>
#include <math.h>

#define NN 6000
#define EE 100000

typedef unsigned long long ull;

// ---------------- f32x2 packed-FMA helpers (sm_103a FFMA2) ----------------------
__device__ __forceinline__ void fma2(ull& d, ull a, ull b) {
    asm("fma.rn.f32x2 %0, %1, %2, %0;" : "+l"(d) : "l"(a), "l"(b));
}
__device__ __forceinline__ ull pack2(float lo, float hi) {
    ull r; asm("mov.b64 %0, {%1, %2};" : "=l"(r) : "f"(lo), "f"(hi)); return r;
}
__device__ __forceinline__ float2 unpack2(ull v) {
    float2 r; asm("mov.b64 {%0, %1}, %2;" : "=f"(r.x), "=f"(r.y) : "l"(v)); return r;
}

// ---------------- scratch (device globals; no allocations allowed) -------------
__device__ float g_H[2 * NN * 64];     // per-relation H matrices (holds W0 for layer 0)
__device__ float g_base[NN * 64];      // x @ root
__device__ float g_xA[NN * 64];
__device__ float g_xB[NN * 64];
__device__ float g_Wr1[2 * 32 * 64];
__device__ float g_Wr2[2 * 64 * 64];
__device__ float g_Wr3[2 * 64 * 32];
__device__ float g_h[NN * 512];        // GAT projected features
__device__ float g_xg[NN * 512];       // GAT output
__device__ float g_ab[NN * 256];       // [A | B] for edge MLP
__device__ float g_asv[NN];
__device__ float g_adv[NN];
__device__ float g_ps[32];
__device__ float g_pd[32];
__device__ float g_cnt[NN * 2];        // per-relation in-counts (float)
__device__ int   g_deg[NN];
__device__ int   g_rowptr[NN + 1];
__device__ int   g_cursor[NN];
__device__ int   g_csrc[EE];
__device__ int   g_ctype[EE];

// ---------------- prep: zero + all wcomp + projected attention vectors ----------
// segments: [0, 384000)          W0 = comp0-combined basis0 rows (into g_H)
//           [384000, +4096)      Wr1
//           [..., +8192)         Wr2
//           [..., +4096)         Wr3
//           [..., +18000)        zero deg (6000 int) + cnt (12000 float)
//           [..., +2048)         p_s / p_d : 64 warps, warp w computes dot #w
#define PREP_TOTAL (384000 + 4096 + 8192 + 4096 + 18000 + 2048)

__global__ void prep_kernel(const float* __restrict__ basis0, const float* __restrict__ comp0,
                            const float* __restrict__ basis1, const float* __restrict__ comp1,
                            const float* __restrict__ basis2, const float* __restrict__ comp2,
                            const float* __restrict__ basis3, const float* __restrict__ comp3,
                            const float* __restrict__ gw, const float* __restrict__ a_s,
                            const float* __restrict__ a_d,
                            float* __restrict__ W0, float* __restrict__ Wr1,
                            float* __restrict__ Wr2, float* __restrict__ Wr3,
                            int* __restrict__ deg, float* __restrict__ cnt,
                            float* __restrict__ ps, float* __restrict__ pd) {
    int idx = blockIdx.x * blockDim.x + threadIdx.x;
    if (idx < 384000) {
        int r = idx / 192000, io = idx - r * 192000;
        float s = 0.f;
#pragma unroll
        for (int b = 0; b < 4; b++) s += comp0[r * 4 + b] * basis0[b * 192000 + io];
        W0[idx] = s;
        return;
    }
    idx -= 384000;
    if (idx < 4096) {
        int r = idx / 2048, io = idx - r * 2048;
        float s = 0.f;
#pragma unroll
        for (int b = 0; b < 4; b++) s += comp1[r * 4 + b] * basis1[b * 2048 + io];
        Wr1[idx] = s;
        return;
    }
    idx -= 4096;
    if (idx < 8192) {
        int r = idx / 4096, io = idx - r * 4096;
        float s = 0.f;
#pragma unroll
        for (int b = 0; b < 4; b++) s += comp2[r * 4 + b] * basis2[b * 4096 + io];
        Wr2[idx] = s;
        return;
    }
    idx -= 8192;
    if (idx < 4096) {
        int r = idx / 2048, io = idx - r * 2048;
        float s = 0.f;
#pragma unroll
        for (int b = 0; b < 4; b++) s += comp3[r * 4 + b] * basis3[b * 2048 + io];
        Wr3[idx] = s;
        return;
    }
    idx -= 4096;
    if (idx < 18000) {
        if (idx < 6000) deg[idx] = 0;
        else cnt[idx - 6000] = 0.f;
        return;
    }
    idx -= 18000;
    if (idx < 2048) {
        int w = idx >> 5, lane = idx & 31;
        int i = w & 31;
        const float* a = (w < 32) ? a_s : a_d;
        float s = 0.f;
        for (int c = lane; c < 512; c += 32) s += gw[i * 512 + c] * a[c];
#pragma unroll
        for (int off = 16; off > 0; off >>= 1) s += __shfl_down_sync(0xffffffffu, s, off);
        if (lane == 0) { if (w < 32) ps[i] = s; else pd[i] = s; }
    }
}

// ---------------- CSR build ----------------------------------------------------
__global__ void count_kernel(const int* __restrict__ ei, const int* __restrict__ et,
                             int* deg, float* cnt) {
    int e = blockIdx.x * blockDim.x + threadIdx.x;
    if (e >= EE) return;
    int d = ei[EE + e];
    atomicAdd(&deg[d], 1);
    atomicAdd(&cnt[d * 2 + et[e]], 1.0f);
}

__global__ void scan_kernel(const int* __restrict__ deg, int* rowptr, int* cursor) {
    int t = threadIdx.x;  // 1024
    int base = t * 6;
    int loc[6];
    int sum = 0;
#pragma unroll
    for (int i = 0; i < 6; i++) {
        int idx = base + i;
        int v = (idx < NN) ? deg[idx] : 0;
        loc[i] = sum;
        sum += v;
    }
    int lane = t & 31, w = t >> 5;
    int v = sum;
#pragma unroll
    for (int off = 1; off < 32; off <<= 1) {
        int n = __shfl_up_sync(0xffffffffu, v, off);
        if (lane >= off) v += n;
    }
    __shared__ int wsum[32];
    if (lane == 31) wsum[w] = v;
    __syncthreads();
    if (w == 0) {
        int x = wsum[lane];
#pragma unroll
        for (int off = 1; off < 32; off <<= 1) {
            int n = __shfl_up_sync(0xffffffffu, x, off);
            if (lane >= off) x += n;
        }
        wsum[lane] = x;
    }
    __syncthreads();
    int incl = v + (w > 0 ? wsum[w - 1] : 0);
    int excl = incl - sum;
#pragma unroll
    for (int i = 0; i < 6; i++) {
        int idx = base + i;
        if (idx < NN) { rowptr[idx] = excl + loc[i]; cursor[idx] = excl + loc[i]; }
    }
    if (t == 1023) rowptr[NN] = incl;
}

__global__ void fill_kernel(const int* __restrict__ ei, const int* __restrict__ et,
                            int* cursor, int* csrc, int* ctype) {
    int e = blockIdx.x * blockDim.x + threadIdx.x;
    if (e >= EE) return;
    int s = ei[e];
    int d = ei[EE + e];
    int pos = atomicAdd(&cursor[d], 1);
    csrc[pos] = s;
    ctype[pos] = et[e];
}

// ---------------- RGCN ---------------------------------------------------------
// H[r] = x @ Wr[r], base = x @ root. Block: 256 threads, M=16 nodes.
template<int IN, int OUT>
__global__ __launch_bounds__(256) void dense_rgcn(const float* __restrict__ x,
                                                  const float* __restrict__ Wr,
                                                  const float* __restrict__ root,
                                                  float* __restrict__ H, float* __restrict__ base) {
    constexpr int M = 16;
    constexpr int G = 256 / OUT;       // groups of OUT threads
    constexpr int P = (M / 2) / G;     // node-pairs per thread
    __shared__ float wsh[2 * IN * OUT];
    __shared__ float xsT[IN][M];
    const int tid = threadIdx.x;
    const int n0 = blockIdx.x * M;
    for (int i = tid; i < IN * OUT; i += 256) {
        wsh[i] = Wr[i];
        wsh[IN * OUT + i] = Wr[IN * OUT + i];
    }
    for (int i = tid; i < M * IN; i += 256) {
        int m = i / IN, k = i - m * IN;
        xsT[k][m] = x[(n0 + m) * IN + k];
    }
    __syncthreads();
    const int o = tid & (OUT - 1);
    const int g = tid / OUT;
    ull a0[P], a1[P], ar[P];
#pragma unroll
    for (int p = 0; p < P; p++) { a0[p] = 0; a1[p] = 0; ar[p] = 0; }
    for (int i = 0; i < IN; i++) {
        float w0 = wsh[i * OUT + o];
        float w1 = wsh[IN * OUT + i * OUT + o];
        float wr = __ldg(&root[i * OUT + o]);
        ull w0d = pack2(w0, w0), w1d = pack2(w1, w1), wrd = pack2(wr, wr);
#pragma unroll
        for (int p = 0; p < P; p++) {
            ull xp = *(const ull*)&xsT[i][2 * (g * P + p)];
            fma2(a0[p], xp, w0d);
            fma2(a1[p], xp, w1d);
            fma2(ar[p], xp, wrd);
        }
    }
#pragma unroll
    for (int p = 0; p < P; p++) {
        int n = n0 + 2 * (g * P + p);
        float2 v0 = unpack2(a0[p]), v1 = unpack2(a1[p]), vr = unpack2(ar[p]);
        H[n * OUT + o] = v0.x;       H[(n + 1) * OUT + o] = v0.y;
        H[(NN + n) * OUT + o] = v1.x; H[(NN + n + 1) * OUT + o] = v1.y;
        base[n * OUT + o] = vr.x;     base[(n + 1) * OUT + o] = vr.y;
    }
}

// per-node per-relation mean aggregation + tanh
__global__ void agg_rgcn(const float* __restrict__ H, const float* __restrict__ base,
                         const float* __restrict__ bias, const float* __restrict__ cnt,
                         const int* __restrict__ rowptr, const int* __restrict__ csrc,
                         const int* __restrict__ ctype,
                         float* __restrict__ xout, int out) {
    int m = threadIdx.y;
    int n = blockIdx.x * blockDim.y + m;
    int o = threadIdx.x;
    float a0 = 0.f, a1 = 0.f;
    int e0 = rowptr[n], e1 = rowptr[n + 1];
    for (int e = e0; e < e1; e++) {
        int s = csrc[e];
        int t = ctype[e];
        float v = H[(t * NN + s) * out + o];
        if (t == 0) a0 += v; else a1 += v;
    }
    float c0 = fmaxf(cnt[n * 2 + 0], 1.f);
    float c1 = fmaxf(cnt[n * 2 + 1], 1.f);
    xout[n * out + o] = tanhf(base[n * out + o] + bias[o] + a0 / c0 + a1 / c1);
}

// ---------------- GAT ----------------------------------------------------------
__device__ __forceinline__ float lrelu02(float a) { return a > 0.f ? a : 0.2f * a; }

// Block: 512 threads (cols), M=40 nodes; gw column cached in registers,
// asv/adv via precomputed p_s/p_d 32-vectors.
__global__ __launch_bounds__(512) void gat_h_kernel(const float* __restrict__ x,
                                                    const float* __restrict__ gw,
                                                    const float* __restrict__ ps,
                                                    const float* __restrict__ pd,
                                                    float* __restrict__ h,
                                                    float* __restrict__ asv, float* __restrict__ adv) {
    __shared__ float xsT[32][40];
    const int c = threadIdx.x;
    const int n0 = blockIdx.x * 40;
    for (int i = c; i < 40 * 32; i += 512) {
        int m = i >> 5, k = i & 31;
        xsT[k][m] = x[(n0 + m) * 32 + k];
    }
    __syncthreads();
    ull gwd[32];
#pragma unroll
    for (int k = 0; k < 32; k++) {
        float g = gw[k * 512 + c];
        gwd[k] = pack2(g, g);
    }
#pragma unroll 4
    for (int mp = 0; mp < 20; mp++) {
        ull acc = 0;
#pragma unroll
        for (int k = 0; k < 32; k++) {
            ull xp = *(const ull*)&xsT[k][2 * mp];
            fma2(acc, xp, gwd[k]);
        }
        float2 v = unpack2(acc);
        h[(size_t)(n0 + 2 * mp) * 512 + c] = v.x;
        h[(size_t)(n0 + 2 * mp + 1) * 512 + c] = v.y;
    }
    if (c < 40) {
        float s = 0.f, t = 0.f;
#pragma unroll
        for (int k = 0; k < 32; k++) {
            float xv = xsT[k][c];
            s += xv * __ldg(&ps[k]);
            t += xv * __ldg(&pd[k]);
        }
        asv[n0 + c] = s;
        adv[n0 + c] = t;
    }
}

__global__ void gat_agg_kernel(const float* __restrict__ h, const float* __restrict__ asv,
                               const float* __restrict__ adv,
                               const int* __restrict__ rowptr, const int* __restrict__ csrc,
                               const float* __restrict__ gbias, float* __restrict__ xout) {
    int n = blockIdx.x;
    int t = threadIdx.x;  // 128 threads, float4 per thread
    int e0 = rowptr[n], e1 = rowptr[n + 1];
    float advn = adv[n];
    float aself = lrelu02(asv[n] + advn);
    float lm = aself;
    for (int e = e0 + t; e < e1; e += 128) lm = fmaxf(lm, lrelu02(asv[csrc[e]] + advn));
    __shared__ float sred[128];
    sred[t] = lm;
    __syncthreads();
    for (int off = 64; off > 0; off >>= 1) {
        if (t < off) sred[t] = fmaxf(sred[t], sred[t + off]);
        __syncthreads();
    }
    float m = sred[0];
    __shared__ float sEx[128];
    __shared__ int sSrc[128];
    float4 acc = make_float4(0.f, 0.f, 0.f, 0.f);
    float denom = 0.f;
    for (int eb = e0; eb < e1; eb += 128) {
        int cnt = min(128, e1 - eb);
        __syncthreads();
        if (t < cnt) {
            int s = csrc[eb + t];
            sSrc[t] = s;
            sEx[t] = expf(lrelu02(asv[s] + advn) - m);
        }
        __syncthreads();
        for (int j = 0; j < cnt; j++) {
            float ex = sEx[j];
            const float4* hr = reinterpret_cast<const float4*>(h + (size_t)sSrc[j] * 512);
            float4 v = hr[t];
            acc.x += ex * v.x; acc.y += ex * v.y; acc.z += ex * v.z; acc.w += ex * v.w;
            denom += ex;
        }
    }
    float exs = expf(aself - m);
    denom += exs;
    {
        const float4* hn = reinterpret_cast<const float4*>(h + (size_t)n * 512);
        float4 v = hn[t];
        acc.x += exs * v.x; acc.y += exs * v.y; acc.z += exs * v.z; acc.w += exs * v.w;
    }
    float inv = 1.f / fmaxf(denom, 1e-16f);
    float4 g = reinterpret_cast<const float4*>(gbias)[t];
    float4 o;
    o.x = fmaxf(acc.x * inv + g.x, 0.f);
    o.y = fmaxf(acc.y * inv + g.y, 0.f);
    o.z = fmaxf(acc.z * inv + g.z, 0.f);
    o.w = fmaxf(acc.w * inv + g.w, 0.f);
    reinterpret_cast<float4*>(xout + (size_t)n * 512)[t] = o;
}

// ---------------- edge MLP ------------------------------------------------------
// AB[n,0:128] = xg[n] @ w1[0:512,:]; AB[n,128:256] = xg[n] @ w1[512:1024,:]
// Block: 256 threads (cols), M=40 nodes, f32x2 node-pair accumulators.
__global__ __launch_bounds__(256) void gemm_ab_kernel(const float* __restrict__ xg,
                                                      const float* __restrict__ w1,
                                                      float* __restrict__ ab) {
    __shared__ float xsT[32][40];
    __shared__ float ws[32][256];
    const int c = threadIdx.x;
    const int n0 = blockIdx.x * 40;
    ull acc[20];
#pragma unroll
    for (int p = 0; p < 20; p++) acc[p] = 0;
    for (int k0 = 0; k0 < 512; k0 += 32) {
        __syncthreads();
        for (int i = c; i < 40 * 32; i += 256) {
            int m = i >> 5, kk = i & 31;
            xsT[kk][m] = xg[(size_t)(n0 + m) * 512 + k0 + kk];
        }
        for (int i = c; i < 32 * 256; i += 256) {
            int kk = i >> 8, cc = i & 255;
            int krow = k0 + kk + ((cc < 128) ? 0 : 512);
            int col = cc & 127;
            ws[kk][cc] = w1[krow * 128 + col];
        }
        __syncthreads();
#pragma unroll 8
        for (int kk = 0; kk < 32; kk++) {
            float wv = ws[kk][c];
            ull wd = pack2(wv, wv);
            const float* xr = &xsT[kk][0];
#pragma unroll
            for (int p = 0; p < 20; p++) {
                ull xp = *(const ull*)(xr + 2 * p);
                fma2(acc[p], xp, wd);
            }
        }
    }
#pragma unroll
    for (int p = 0; p < 20; p++) {
        float2 v = unpack2(acc[p]);
        ab[(size_t)(n0 + 2 * p) * 256 + c] = v.x;
        ab[(size_t)(n0 + 2 * p + 1) * 256 + c] = v.y;
    }
}

// warp per edge: out = sigmoid( relu(A[src]+B[dst]+b1) . w2 + b2 )
__global__ void edge_kernel(const int* __restrict__ ei, const float* __restrict__ ab,
                            const float* __restrict__ b1, const float* __restrict__ w2,
                            const float* __restrict__ b2, float* __restrict__ out) {
    int gid = blockIdx.x * blockDim.x + threadIdx.x;
    int e = gid >> 5;
    int lane = gid & 31;
    if (e >= EE) return;
    int s = ei[e];
    int d = ei[EE + e];
    float4 a = reinterpret_cast<const float4*>(ab + (size_t)s * 256)[lane];
    float4 bv = reinterpret_cast<const float4*>(ab + (size_t)d * 256 + 128)[lane];
    float4 bb = reinterpret_cast<const float4*>(b1)[lane];
    float4 wv = reinterpret_cast<const float4*>(w2)[lane];
    float acc = fmaxf(a.x + bv.x + bb.x, 0.f) * wv.x
              + fmaxf(a.y + bv.y + bb.y, 0.f) * wv.y
              + fmaxf(a.z + bv.z + bb.z, 0.f) * wv.z
              + fmaxf(a.w + bv.w + bb.w, 0.f) * wv.w;
#pragma unroll
    for (int off = 16; off > 0; off >>= 1) acc += __shfl_down_sync(0xffffffffu, acc, off);
    if (lane == 0) out[e] = 1.f / (1.f + expf(-(acc + b2[0])));
}

// ---------------- launch ---------------------------------------------------------
extern "C" void kernel_launch(void* const* d_in, const int* in_sizes, int n_in,
                              void* d_out, int out_size) {
    const float *basis[4], *comp[4], *root[4], *rbias[4];
    const float *gat_w, *att_s, *att_d, *gat_b, *w1, *b1, *w2, *b2;
    const int *ei, *et;

    if (in_sizes[0] == 2 * EE) {
        ei = (const int*)d_in[0];
        et = (const int*)d_in[1];
        int k = 2;
        for (int l = 0; l < 4; l++) {
            basis[l] = (const float*)d_in[k++];
            comp[l]  = (const float*)d_in[k++];
            root[l]  = (const float*)d_in[k++];
            rbias[l] = (const float*)d_in[k++];
        }
        gat_w = (const float*)d_in[18]; att_s = (const float*)d_in[19];
        att_d = (const float*)d_in[20]; gat_b = (const float*)d_in[21];
        w1 = (const float*)d_in[22]; b1 = (const float*)d_in[23];
        w2 = (const float*)d_in[24]; b2 = (const float*)d_in[25];
    } else if (in_sizes[0] == 4 * NN * 32) {
        int k = 0;
        for (int l = 0; l < 4; l++) {
            basis[l] = (const float*)d_in[k++];
            comp[l]  = (const float*)d_in[k++];
            root[l]  = (const float*)d_in[k++];
            rbias[l] = (const float*)d_in[k++];
        }
        gat_w = (const float*)d_in[16]; att_s = (const float*)d_in[17];
        att_d = (const float*)d_in[18]; gat_b = (const float*)d_in[19];
        w1 = (const float*)d_in[20]; b1 = (const float*)d_in[21];
        w2 = (const float*)d_in[22]; b2 = (const float*)d_in[23];
        ei = (const int*)d_in[24]; et = (const int*)d_in[25];
    } else {
        b1 = (const float*)d_in[0]; b2 = (const float*)d_in[1];
        for (int l = 0; l < 4; l++) basis[l] = (const float*)d_in[2 + l];
        for (int l = 0; l < 4; l++) comp[l] = (const float*)d_in[6 + l];
        ei = (const int*)d_in[10]; et = (const int*)d_in[11];
        att_d = (const float*)d_in[12]; att_s = (const float*)d_in[13];
        gat_b = (const float*)d_in[14]; gat_w = (const float*)d_in[15];
        for (int l = 0; l < 4; l++) rbias[l] = (const float*)d_in[16 + l];
        for (int l = 0; l < 4; l++) root[l] = (const float*)d_in[20 + l];
        w1 = (const float*)d_in[24]; w2 = (const float*)d_in[25];
    }

    float *H, *base, *xA, *xB, *Wr1, *Wr2, *Wr3, *h, *xg, *ab, *asv, *adv, *cnt, *ps, *pd;
    int *deg, *rowptr, *cursor, *csrc, *ctype;
    cudaGetSymbolAddress((void**)&H, g_H);
    cudaGetSymbolAddress((void**)&base, g_base);
    cudaGetSymbolAddress((void**)&xA, g_xA);
    cudaGetSymbolAddress((void**)&xB, g_xB);
    cudaGetSymbolAddress((void**)&Wr1, g_Wr1);
    cudaGetSymbolAddress((void**)&Wr2, g_Wr2);
    cudaGetSymbolAddress((void**)&Wr3, g_Wr3);
    cudaGetSymbolAddress((void**)&h, g_h);
    cudaGetSymbolAddress((void**)&xg, g_xg);
    cudaGetSymbolAddress((void**)&ab, g_ab);
    cudaGetSymbolAddress((void**)&asv, g_asv);
    cudaGetSymbolAddress((void**)&adv, g_adv);
    cudaGetSymbolAddress((void**)&ps, g_ps);
    cudaGetSymbolAddress((void**)&pd, g_pd);
    cudaGetSymbolAddress((void**)&cnt, g_cnt);
    cudaGetSymbolAddress((void**)&deg, g_deg);
    cudaGetSymbolAddress((void**)&rowptr, g_rowptr);
    cudaGetSymbolAddress((void**)&cursor, g_cursor);
    cudaGetSymbolAddress((void**)&csrc, g_csrc);
    cudaGetSymbolAddress((void**)&ctype, g_ctype);

    float* out = (float*)d_out;

    // ---- fused prep (zero + all basis combinations + p_s/p_d) ----
    prep_kernel<<<(PREP_TOTAL + 255) / 256, 256>>>(
        basis[0], comp[0], basis[1], comp[1], basis[2], comp[2], basis[3], comp[3],
        gat_w, att_s, att_d, H, Wr1, Wr2, Wr3, deg, cnt, ps, pd);

    // ---- CSR build ----
    count_kernel<<<(EE + 255) / 256, 256>>>(ei, et, deg, cnt);
    scan_kernel<<<1, 1024>>>(deg, rowptr, cursor);
    fill_kernel<<<(EE + 255) / 256, 256>>>(ei, et, cursor, csrc, ctype);

    // ---- Layer 0 (x = I shortcut): H = W0, base = root0 ----
    agg_rgcn<<<NN / 8, dim3(32, 8)>>>(H, root[0], rbias[0], cnt, rowptr, csrc, ctype, xA, 32);

    // ---- Layer 1: 32 -> 64 ----
    dense_rgcn<32, 64><<<NN / 16, 256>>>(xA, Wr1, root[1], H, base);
    agg_rgcn<<<NN / 4, dim3(64, 4)>>>(H, base, rbias[1], cnt, rowptr, csrc, ctype, xB, 64);

    // ---- Layer 2: 64 -> 64 ----
    dense_rgcn<64, 64><<<NN / 16, 256>>>(xB, Wr2, root[2], H, base);
    agg_rgcn<<<NN / 4, dim3(64, 4)>>>(H, base, rbias[2], cnt, rowptr, csrc, ctype, xA, 64);

    // ---- Layer 3: 64 -> 32 ----
    dense_rgcn<64, 32><<<NN / 16, 256>>>(xA, Wr3, root[3], H, base);
    agg_rgcn<<<NN / 8, dim3(32, 8)>>>(H, base, rbias[3], cnt, rowptr, csrc, ctype, xB, 32);

    // ---- GAT ----
    gat_h_kernel<<<NN / 40, 512>>>(xB, gat_w, ps, pd, h, asv, adv);
    gat_agg_kernel<<<NN, 128>>>(h, asv, adv, rowptr, csrc, gat_b, xg);

    // ---- edge MLP (factorized: feat@w1 = A[src] + B[dst]) ----
    gemm_ab_kernel<<<NN / 40, 256>>>(xg, w1, ab);
    edge_kernel<<<(EE * 32 + 255) / 256, 256>>>(ei, ab, b1, w2, b2, out);
}